// round 3
// baseline (speedup 1.0000x reference)
#include <cuda_runtime.h>
#include <cstdint>

static constexpr int K_TOTAL = 1280, N_TOTAL = 1280;
static constexpr int BM = 128, BN = 256;
static constexpr int SLICES = 40;               // K / 32
static constexpr int NTILES = 5, MTILES = 512;
static constexpr int GRID = NTILES * MTILES;    // 2560
static constexpr int THREADS = 256;

// smem byte offsets (double buffered)
static constexpr int A_ST = 16384, B_ST = 32768, B2_ST = 1024;
static constexpr int OFF_A = 0;
static constexpr int OFF_B = 32768;
static constexpr int OFF_B2 = 98304;
static constexpr int OFF_WU = 100352;   // 4 KB
static constexpr int OFF_DN = 104448;   // 2 KB
static constexpr int SMEM_BYTES = 106496;

// W in fragment order: [ntile][slice][wc][nf][ks][lane][2]
__device__ __align__(16) float g_Wfrag[NTILES * SLICES * 8192];
// Wd in fragment order: [lora][slice][ks][lane][2] (cols 4..7 zero)
__device__ __align__(16) float g_Wdfrag[50 * SLICES * 256];

__device__ __forceinline__ uint32_t smem_u32(const void* p) {
    uint32_t a;
    asm("{ .reg .u64 t; cvta.to.shared.u64 t, %1; cvt.u32.u64 %0, t; }" : "=r"(a) : "l"(p));
    return a;
}
__device__ __forceinline__ uint32_t rna(float f) {
    uint32_t b;
    asm("cvt.rna.tf32.f32 %0, %1;" : "=r"(b) : "f"(f));
    return b;
}
__device__ __forceinline__ void mma8(float* c, const uint32_t* a, const uint32_t* b) {
    asm volatile(
        "mma.sync.aligned.m16n8k8.row.col.f32.tf32.tf32.f32 "
        "{%0,%1,%2,%3}, {%4,%5,%6,%7}, {%8,%9}, {%0,%1,%2,%3};"
        : "+f"(c[0]), "+f"(c[1]), "+f"(c[2]), "+f"(c[3])
        : "r"(a[0]), "r"(a[1]), "r"(a[2]), "r"(a[3]), "r"(b[0]), "r"(b[1]));
}
#define CP16(d, s) asm volatile("cp.async.cg.shared.global [%0], [%1], 16;" :: "r"(d), "l"(s))
#define CP4(d, s)  asm volatile("cp.async.ca.shared.global [%0], [%1], 4;"  :: "r"(d), "l"(s))
#define CP_COMMIT() asm volatile("cp.async.commit_group;")
#define CP_WAIT0()  asm volatile("cp.async.wait_group 0;" ::: "memory")

// ---------------- prepass: rna-round W/Wd and scatter into fragment layout
__global__ void prep_kernel(const float* __restrict__ W, const float* __restrict__ Wd) {
    int i = blockIdx.x * blockDim.x + threadIdx.x;
    const int NW = N_TOTAL * K_TOTAL;
    if (i < NW) {
        int n = i / K_TOTAL, k = i % K_TOTAL;
        int ntile = n >> 8, nn = n & 255, wc = nn >> 6, nf = (nn >> 3) & 7, gid = nn & 7;
        int slice = k >> 5, ks = (k >> 3) & 3, kh = (k >> 2) & 1, tig = k & 3;
        int off = (ntile * SLICES + slice) * 8192 +
                  (((wc * 8 + nf) * 4 + ks) * 32 + gid * 4 + tig) * 2 + kh;
        g_Wfrag[off] = __uint_as_float(rna(W[i]));
    } else if (i < NW + 50 * K_TOTAL * 8) {
        int j = i - NW;
        int gid = j & 7, t = j >> 3, k = t % K_TOTAL, l = t / K_TOTAL;
        float v = 0.f;
        if (gid < 4) v = __uint_as_float(rna(Wd[(l * 4 + gid) * K_TOTAL + k]));
        int slice = k >> 5, ks = (k >> 3) & 3, kh = (k >> 2) & 1, tig = k & 3;
        g_Wdfrag[(l * SLICES + slice) * 256 + (ks * 32 + gid * 4 + tig) * 2 + kh] = v;
    }
}

// ---------------- main fused kernel
__global__ void __launch_bounds__(THREADS, 1)
lora_gemm(const float* __restrict__ x, const int* __restrict__ lora_id,
          const float* __restrict__ Wu, float* __restrict__ out) {
    extern __shared__ char smem[];
    const uint32_t sb = smem_u32(smem);
    const int tid = threadIdx.x, lane = tid & 31, wid = tid >> 5;
    const int bid = blockIdx.x;
    const int ntile = bid % NTILES, mtile = bid / NTILES;
    const int m0 = mtile * BM, nb = ntile * BN;

    const int id = lora_id[m0 >> 12];
    const int idx = (id >= 0) ? ((id >> 2) > 49 ? 49 : (id >> 2)) : 0;
    const float coeff = (id >= 0) ? 1.f : 0.f;

    // stage Wu tile (full fp32) into smem: 256 float4
    {
        const float4* wusrc = (const float4*)Wu + (size_t)idx * N_TOTAL + nb;
        ((float4*)(smem + OFF_WU))[tid] = wusrc[tid];
    }

    const int gid = lane >> 2, tig = lane & 3;
    const int wr = wid >> 2, wc = wid & 3;

    // producer indexing (A): thread -> (row, k-half)
    const int pr = tid >> 1, pq = tid & 1;
    const float* xrow = x + (size_t)(m0 + pr) * K_TOTAL + pq * 16;
    const int awr = pr >> 6, amf = (pr >> 4) & 3, agid = pr & 7, ah = (pr >> 3) & 1;
    const uint32_t asts_base = sb + OFF_A + (((awr * 4 + amf) * 4) * 32 + agid * 4) * 16;

    const float* wsrc = g_Wfrag + (size_t)ntile * SLICES * 8192;
    const float* wdsrc = g_Wdfrag + (size_t)idx * SLICES * 256;

    float acc[4][8][4];
    float accL[4][4];
    #pragma unroll
    for (int a = 0; a < 4; ++a) {
        #pragma unroll
        for (int b = 0; b < 8; ++b)
            acc[a][b][0] = acc[a][b][1] = acc[a][b][2] = acc[a][b][3] = 0.f;
        accL[a][0] = accL[a][1] = accL[a][2] = accL[a][3] = 0.f;
    }

    // ---- preload slice 0 into stage 0
    {
        CP4(sb + OFF_B2 + tid * 4, wdsrc + tid);
        #pragma unroll
        for (int c = 0; c < 8; ++c)
            CP16(sb + OFF_B + tid * 128 + c * 16, wsrc + tid * 32 + c * 4);
        CP_COMMIT();
        #pragma unroll
        for (int j = 0; j < 4; ++j) {
            float4 v = ((const float4*)xrow)[j];
            int q = pq * 4 + j, ksj = q >> 1, khj = q & 1;
            float* ap = (float*)(smem + OFF_A) +
                        ((((awr * 4 + amf) * 4 + ksj) * 32 + agid * 4) * 16 +
                         (ah + 2 * khj) * 4) / 4;
            ap[0] = __uint_as_float(rna(v.x));
            ap[4] = __uint_as_float(rna(v.y));
            ap[8] = __uint_as_float(rna(v.z));
            ap[12] = __uint_as_float(rna(v.w));
        }
        CP_WAIT0();
        __syncthreads();
    }

    // ---- main loop
    #pragma unroll 1
    for (int s = 0; s < SLICES; ++s) {
        const int cur = s & 1, nxt = cur ^ 1;
        const bool pf = (s + 1) < SLICES;
        float4 av[4];
        if (pf) {
            const float* xp = xrow + (s + 1) * 32;
            #pragma unroll
            for (int j = 0; j < 4; ++j) av[j] = ((const float4*)xp)[j];
            const float* wp = wsrc + (size_t)(s + 1) * 8192;
            CP4(sb + OFF_B2 + nxt * B2_ST + tid * 4, wdsrc + (s + 1) * 256 + tid);
            #pragma unroll
            for (int c = 0; c < 8; ++c)
                CP16(sb + OFF_B + nxt * B_ST + tid * 128 + c * 16, wp + tid * 32 + c * 4);
            CP_COMMIT();
        }
        // compute on cur
        const uint32_t abase = sb + OFF_A + cur * A_ST + ((wr * 16) * 32 + lane) * 16;
        const uint32_t bbase = sb + OFF_B + cur * B_ST + ((wc * 32) * 32 + lane) * 8;
        const uint32_t b2base = sb + OFF_B2 + cur * B2_ST + lane * 8;
        #pragma unroll
        for (int ks = 0; ks < 4; ++ks) {
            uint32_t a[4][4];
            #pragma unroll
            for (int mf = 0; mf < 4; ++mf)
                asm volatile("ld.shared.v4.b32 {%0,%1,%2,%3}, [%4];"
                             : "=r"(a[mf][0]), "=r"(a[mf][1]), "=r"(a[mf][2]), "=r"(a[mf][3])
                             : "r"(abase + ((mf * 4 + ks) * 32) * 16));
            #pragma unroll
            for (int nf = 0; nf < 8; ++nf) {
                uint32_t b[2];
                asm volatile("ld.shared.v2.b32 {%0,%1}, [%2];"
                             : "=r"(b[0]), "=r"(b[1])
                             : "r"(bbase + ((nf * 4 + ks) * 32) * 8));
                #pragma unroll
                for (int mf = 0; mf < 4; ++mf) mma8(acc[mf][nf], a[mf], b);
            }
            if (wc == 0) {
                uint32_t b2[2];
                asm volatile("ld.shared.v2.b32 {%0,%1}, [%2];"
                             : "=r"(b2[0]), "=r"(b2[1]) : "r"(b2base + (ks * 32) * 8));
                #pragma unroll
                for (int mf = 0; mf < 4; ++mf) mma8(accL[mf], a[mf], b2);
            }
        }
        if (pf) {
            float* ast = (float*)(smem + OFF_A + nxt * A_ST);
            #pragma unroll
            for (int j = 0; j < 4; ++j) {
                int q = pq * 4 + j, ksj = q >> 1, khj = q & 1;
                float* ap = ast + ((((awr * 4 + amf) * 4 + ksj) * 32 + agid * 4) * 16 +
                                   (ah + 2 * khj) * 4) / 4;
                ap[0] = __uint_as_float(rna(av[j].x));
                ap[4] = __uint_as_float(rna(av[j].y));
                ap[8] = __uint_as_float(rna(av[j].z));
                ap[12] = __uint_as_float(rna(av[j].w));
            }
        }
        CP_WAIT0();
        __syncthreads();
    }

    // ---- epilogue: stage lora-down, then fused add + store
    float* dns = (float*)(smem + OFF_DN);
    if (wc == 0 && tig < 2) {
        #pragma unroll
        for (int mf = 0; mf < 4; ++mf) {
            int mlo = wr * 64 + mf * 16 + gid, mhi = mlo + 8;
            dns[mlo * 4 + 2 * tig] = accL[mf][0] * coeff;
            dns[mlo * 4 + 2 * tig + 1] = accL[mf][1] * coeff;
            dns[mhi * 4 + 2 * tig] = accL[mf][2] * coeff;
            dns[mhi * 4 + 2 * tig + 1] = accL[mf][3] * coeff;
        }
    }
    __syncthreads();

    const float4* wus = (const float4*)(smem + OFF_WU);
    #pragma unroll
    for (int mf = 0; mf < 4; ++mf) {
        int mlo = wr * 64 + mf * 16 + gid, mhi = mlo + 8;
        float4 dlo = ((const float4*)dns)[mlo];
        float4 dhi = ((const float4*)dns)[mhi];
        float* olo = out + (size_t)(m0 + mlo) * N_TOTAL + nb;
        float* ohi = out + (size_t)(m0 + mhi) * N_TOTAL + nb;
        #pragma unroll
        for (int nf = 0; nf < 8; ++nf) {
            int n = wc * 64 + nf * 8 + 2 * tig;
            float4 w0 = wus[n], w1 = wus[n + 1];
            float2 vlo, vhi;
            vlo.x = acc[mf][nf][0] + dlo.x * w0.x + dlo.y * w0.y + dlo.z * w0.z + dlo.w * w0.w;
            vlo.y = acc[mf][nf][1] + dlo.x * w1.x + dlo.y * w1.y + dlo.z * w1.z + dlo.w * w1.w;
            vhi.x = acc[mf][nf][2] + dhi.x * w0.x + dhi.y * w0.y + dhi.z * w0.z + dhi.w * w0.w;
            vhi.y = acc[mf][nf][3] + dhi.x * w1.x + dhi.y * w1.y + dhi.z * w1.z + dhi.w * w1.w;
            *(float2*)(olo + n) = vlo;
            *(float2*)(ohi + n) = vhi;
        }
    }
}

extern "C" void kernel_launch(void* const* d_in, const int* in_sizes, int n_in,
                              void* d_out, int out_size) {
    const float* x = (const float*)d_in[0];
    const int* lid = (const int*)d_in[1];
    const float* W = (const float*)d_in[2];
    const float* Wd = (const float*)d_in[3];
    const float* Wu = (const float*)d_in[4];
    float* out = (float*)d_out;

    cudaFuncSetAttribute(lora_gemm, cudaFuncAttributeMaxDynamicSharedMemorySize, SMEM_BYTES);
    int total = N_TOTAL * K_TOTAL + 50 * K_TOTAL * 8;
    prep_kernel<<<(total + 255) / 256, 256>>>(W, Wd);
    lora_gemm<<<GRID, THREADS, SMEM_BYTES>>>(x, lid, Wu, out);
}